// round 3
// baseline (speedup 1.0000x reference)
#include <cuda_runtime.h>
#include <cuda_bf16.h>
#include <math.h>

#define TOK 2048
#define DIM 1024
#define TDIM 3072
#define SEQ 512
#define NHEAD 16
#define HDIM 64
#define NEXP 8
#define HID 1792
#define SLOTS 4096

// ------------------------- scratch (device globals) -------------------------
__device__ float g_xn1[TOK * DIM];
__device__ float g_qkv[TOK * TDIM];
__device__ float g_attn[TOK * DIM];
__device__ float g_x1[TOK * DIM];
__device__ float g_xn2[TOK * DIM];
__device__ float g_gbuf[SLOTS * HID];
__device__ float g_ubuf[SLOTS * HID];
__device__ float g_dbuf[SLOTS * DIM];
__device__ float g_cw[TOK * 2];
__device__ int   g_topk[TOK * 2];
__device__ int   g_slot[TOK * 2];
__device__ int   g_perm[SLOTS];
__device__ int   g_cnt[NEXP];
__device__ int   g_off[NEXP];
__device__ int   g_fill[NEXP];
__device__ float g_dist[NEXP];

// ------------------------- small helpers -------------------------
__device__ __forceinline__ float block_sum(float v) {
    __shared__ float red[8];
    #pragma unroll
    for (int o = 16; o; o >>= 1) v += __shfl_xor_sync(0xffffffffu, v, o);
    int w = threadIdx.x >> 5;
    if ((threadIdx.x & 31) == 0) red[w] = v;
    __syncthreads();
    if (threadIdx.x < 32) {
        float t = (threadIdx.x < 8) ? red[threadIdx.x] : 0.f;
        #pragma unroll
        for (int o = 4; o; o >>= 1) t += __shfl_xor_sync(0xffffffffu, t, o);
        if (threadIdx.x == 0) red[0] = t;
    }
    __syncthreads();
    float r = red[0];
    __syncthreads();
    return r;
}

// ------------------------- LayerNorm -------------------------
__global__ void ln_k(const float* __restrict__ x, const float* __restrict__ g,
                     const float* __restrict__ b, float* __restrict__ y) {
    int row = blockIdx.x;
    int tid = threadIdx.x;
    const float* xr = x + (size_t)row * DIM;
    float v[4];
    float s = 0.f;
    #pragma unroll
    for (int i = 0; i < 4; i++) { v[i] = xr[tid + 256 * i]; s += v[i]; }
    float mu = block_sum(s) * (1.f / 1024.f);
    float q = 0.f;
    #pragma unroll
    for (int i = 0; i < 4; i++) { float d = v[i] - mu; q += d * d; }
    float var = block_sum(q) * (1.f / 1024.f);
    float rs = rsqrtf(var + 1e-5f);
    float* yr = y + (size_t)row * DIM;
    #pragma unroll
    for (int i = 0; i < 4; i++) {
        int c = tid + 256 * i;
        yr[c] = (v[i] - mu) * rs * g[c] + b[c];
    }
}

// ------------------------- generic 128x128 SGEMM body -------------------------
__device__ __forceinline__ void gemm_body(
    const float* __restrict__ A, int lda,
    const float* __restrict__ B, int ldb,
    float* __restrict__ C, int ldc,
    const float* __restrict__ R, int ldr,
    const int* __restrict__ rowidx,
    int M, int N, int K, int bm, int bn) {
    __shared__ float As[8][128];
    __shared__ float Bs[8][128];
    const int tid = threadIdx.x;
    const int arow = tid >> 1;
    const int acol = (tid & 1) << 2;
    const int brow = tid >> 5;
    const int bcol = (tid & 31) << 2;
    const int grow = bm * 128 + arow;
    const bool aval = grow < M;
    int arowg = aval ? (rowidx ? rowidx[grow] : grow) : 0;
    const float* Ap = A + (size_t)arowg * lda + acol;
    const float* Bp = B + (size_t)brow * ldb + bn * 128 + bcol;
    const int rb = (tid >> 4) << 3;
    const int cb = (tid & 15) << 3;
    float acc[8][8];
    #pragma unroll
    for (int i = 0; i < 8; i++)
        #pragma unroll
        for (int j = 0; j < 8; j++) acc[i][j] = 0.f;

    for (int kt = 0; kt < K; kt += 8) {
        float4 av = aval ? *(const float4*)(Ap + kt) : make_float4(0.f, 0.f, 0.f, 0.f);
        As[acol + 0][arow] = av.x;
        As[acol + 1][arow] = av.y;
        As[acol + 2][arow] = av.z;
        As[acol + 3][arow] = av.w;
        *(float4*)&Bs[brow][bcol] = *(const float4*)(Bp + (size_t)kt * ldb);
        __syncthreads();
        #pragma unroll
        for (int k = 0; k < 8; k++) {
            float a[8], b[8];
            #pragma unroll
            for (int i = 0; i < 8; i++) a[i] = As[k][rb + i];
            #pragma unroll
            for (int j = 0; j < 8; j++) b[j] = Bs[k][cb + j];
            #pragma unroll
            for (int i = 0; i < 8; i++)
                #pragma unroll
                for (int j = 0; j < 8; j++)
                    acc[i][j] = fmaf(a[i], b[j], acc[i][j]);
        }
        __syncthreads();
    }
    #pragma unroll
    for (int i = 0; i < 8; i++) {
        int row = bm * 128 + rb + i;
        if (row < M) {
            float* Cp = C + (size_t)row * ldc + bn * 128 + cb;
            if (R) {
                const float* Rp = R + (size_t)row * ldr + bn * 128 + cb;
                #pragma unroll
                for (int j = 0; j < 8; j++) Cp[j] = acc[i][j] + Rp[j];
            } else {
                #pragma unroll
                for (int j = 0; j < 8; j++) Cp[j] = acc[i][j];
            }
        }
    }
}

__global__ void sgemm_k(const float* __restrict__ A, const float* __restrict__ B,
                        float* __restrict__ C, const float* __restrict__ R,
                        int M, int N, int K, int lda, int ldb, int ldc, int ldr) {
    gemm_body(A, lda, B, ldb, C, ldc, R, ldr, nullptr, M, N, K, blockIdx.y, blockIdx.x);
}

__global__ void moe_gemm_gather_k(const float* __restrict__ X, const float* __restrict__ W,
                                  float* __restrict__ Cb, int K, int N) {
    int e = blockIdx.z;
    int cnt = g_cnt[e];
    if ((int)(blockIdx.y * 128) >= cnt) return;
    int off = g_off[e];
    gemm_body(X, K, W + (size_t)e * K * N, N, Cb + (size_t)off * N, N,
              nullptr, 0, g_perm + off, cnt, N, K, blockIdx.y, blockIdx.x);
}

__global__ void moe_gemm_dense_k(const float* __restrict__ Xb, const float* __restrict__ W,
                                 float* __restrict__ Cb, int K, int N) {
    int e = blockIdx.z;
    int cnt = g_cnt[e];
    if ((int)(blockIdx.y * 128) >= cnt) return;
    int off = g_off[e];
    gemm_body(Xb + (size_t)off * K, K, W + (size_t)e * K * N, N, Cb + (size_t)off * N, N,
              nullptr, 0, nullptr, cnt, N, K, blockIdx.y, blockIdx.x);
}

// ------------------------- RoPE (in-place on q,k sections of qkv) -------------------------
__global__ void rope_k(float* __restrict__ qkv) {
    int idx = blockIdx.x * blockDim.x + threadIdx.x;
    if (idx >= TOK * NHEAD * 32) return;
    int i = idx & 31;
    int h = (idx >> 5) & 15;
    int row = idx >> 9;
    int s = row & (SEQ - 1);
    double invd = pow(10000.0, -(double)(2 * i) / 64.0);
    float invf = (float)invd;
    float f = (float)s * invf;              // matches reference fp32 outer product
    float c = (float)cos((double)f);
    float sn = (float)sin((double)f);
    float* qp = qkv + (size_t)row * TDIM + h * 64 + 2 * i;
    float xe = qp[0], xo = qp[1];
    qp[0] = xe * c - xo * sn;
    qp[1] = xe * sn + xo * c;
    float* kp = qp + DIM;
    xe = kp[0]; xo = kp[1];
    kp[0] = xe * c - xo * sn;
    kp[1] = xe * sn + xo * c;
}

// ------------------------- flash attention (64x64 tiles, hd=64) -------------------------
__global__ void attn_k(const float* __restrict__ qkv, float* __restrict__ out) {
    extern __shared__ float sm[];
    float* Qs = sm;                 // 64 x 65
    float* Ks = sm + 64 * 65;
    float* Vs = sm + 2 * 64 * 65;
    float* Ps = sm + 3 * 64 * 65;
    int mt = blockIdx.x;
    int b = blockIdx.y >> 4, h = blockIdx.y & 15;
    int tid = threadIdx.x;
    int ty = tid >> 4, tx = tid & 15;
    const size_t rowbase = (size_t)(b * SEQ) * TDIM;

    for (int i = tid; i < 64 * 64; i += 256) {
        int r = i >> 6, c = i & 63;
        Qs[r * 65 + c] = qkv[rowbase + (size_t)(mt * 64 + r) * TDIM + h * 64 + c];
    }
    float m_i[4], l_i[4], o[4][4];
    #pragma unroll
    for (int i = 0; i < 4; i++) {
        m_i[i] = -INFINITY; l_i[i] = 0.f;
        #pragma unroll
        for (int j = 0; j < 4; j++) o[i][j] = 0.f;
    }

    for (int nt = 0; nt <= mt; nt++) {
        __syncthreads();
        for (int i = tid; i < 64 * 64; i += 256) {
            int r = i >> 6, c = i & 63;
            size_t base = rowbase + (size_t)(nt * 64 + r) * TDIM + h * 64 + c;
            Ks[r * 65 + c] = qkv[base + DIM];
            Vs[r * 65 + c] = qkv[base + 2 * DIM];
        }
        __syncthreads();

        float s4[4][4];
        #pragma unroll
        for (int i = 0; i < 4; i++)
            #pragma unroll
            for (int j = 0; j < 4; j++) s4[i][j] = 0.f;
        #pragma unroll 8
        for (int d = 0; d < 64; d++) {
            float a[4], k4[4];
            #pragma unroll
            for (int i = 0; i < 4; i++) a[i] = Qs[(ty * 4 + i) * 65 + d];
            #pragma unroll
            for (int j = 0; j < 4; j++) k4[j] = Ks[(tx * 4 + j) * 65 + d];
            #pragma unroll
            for (int i = 0; i < 4; i++)
                #pragma unroll
                for (int j = 0; j < 4; j++)
                    s4[i][j] = fmaf(a[i], k4[j], s4[i][j]);
        }
        const float scale = 0.125f;
        #pragma unroll
        for (int i = 0; i < 4; i++) {
            #pragma unroll
            for (int j = 0; j < 4; j++) {
                float v = s4[i][j] * scale;
                if (nt == mt && (tx * 4 + j) > (ty * 4 + i)) v = -INFINITY;
                s4[i][j] = v;
            }
            float mx = fmaxf(fmaxf(s4[i][0], s4[i][1]), fmaxf(s4[i][2], s4[i][3]));
            #pragma unroll
            for (int o2 = 8; o2; o2 >>= 1) mx = fmaxf(mx, __shfl_xor_sync(0xffffffffu, mx, o2, 16));
            float mn = fmaxf(m_i[i], mx);
            float alpha = expf(m_i[i] - mn);
            float rsum = 0.f;
            #pragma unroll
            for (int j = 0; j < 4; j++) {
                float p = expf(s4[i][j] - mn);
                Ps[(ty * 4 + i) * 65 + tx * 4 + j] = p;
                rsum += p;
            }
            #pragma unroll
            for (int o2 = 8; o2; o2 >>= 1) rsum += __shfl_xor_sync(0xffffffffu, rsum, o2, 16);
            l_i[i] = l_i[i] * alpha + rsum;
            m_i[i] = mn;
            #pragma unroll
            for (int j = 0; j < 4; j++) o[i][j] *= alpha;
        }
        __syncthreads();
        #pragma unroll 8
        for (int n = 0; n < 64; n++) {
            float p4[4], v4[4];
            #pragma unroll
            for (int i = 0; i < 4; i++) p4[i] = Ps[(ty * 4 + i) * 65 + n];
            #pragma unroll
            for (int j = 0; j < 4; j++) v4[j] = Vs[n * 65 + tx * 4 + j];
            #pragma unroll
            for (int i = 0; i < 4; i++)
                #pragma unroll
                for (int j = 0; j < 4; j++)
                    o[i][j] = fmaf(p4[i], v4[j], o[i][j]);
        }
    }
    #pragma unroll
    for (int i = 0; i < 4; i++) {
        float inv = 1.f / l_i[i];
        #pragma unroll
        for (int j = 0; j < 4; j++)
            out[(size_t)(b * SEQ + mt * 64 + ty * 4 + i) * DIM + h * 64 + tx * 4 + j] = o[i][j] * inv;
    }
}

// ------------------------- MoE gate / routing -------------------------
__global__ void zero_k() {
    int t = threadIdx.x;
    if (t < NEXP) { g_cnt[t] = 0; g_fill[t] = 0; g_dist[t] = 0.f; }
}

__global__ void gate_k(const float* __restrict__ xn2, const float* __restrict__ gw) {
    int t = blockIdx.x;
    int wid = threadIdx.x >> 5, lane = threadIdx.x & 31;
    const float* xr = xn2 + (size_t)t * DIM;
    float acc = 0.f;
    for (int k = lane; k < DIM; k += 32) {
        float a = __bfloat162float(__float2bfloat16(xr[k]));
        float w = __bfloat162float(__float2bfloat16(gw[(size_t)k * NEXP + wid]));
        acc = fmaf(a, w, acc);
    }
    #pragma unroll
    for (int o = 16; o; o >>= 1) acc += __shfl_xor_sync(0xffffffffu, acc, o);
    __shared__ float lg[NEXP];
    if (lane == 0) lg[wid] = __bfloat162float(__float2bfloat16(acc));  // bf16 result like jax
    __syncthreads();
    if (threadIdx.x == 0) {
        float mx = lg[0];
        for (int e = 1; e < NEXP; e++) mx = fmaxf(mx, lg[e]);
        float p[NEXP], sum = 0.f;
        for (int e = 0; e < NEXP; e++) { p[e] = expf(lg[e] - mx); sum += p[e]; }
        float inv = 1.f / sum;
        for (int e = 0; e < NEXP; e++) atomicAdd(&g_dist[e], p[e] * inv);
        int i0 = 0;
        for (int e = 1; e < NEXP; e++) if (lg[e] > lg[i0]) i0 = e;
        int i1 = -1;
        for (int e = 0; e < NEXP; e++) {
            if (e == i0) continue;
            if (i1 < 0 || lg[e] > lg[i1]) i1 = e;
        }
        float eb = expf(lg[i1] - lg[i0]);
        float w0 = 1.f / (1.f + eb);
        g_cw[2 * t] = w0;
        g_cw[2 * t + 1] = eb * w0;
        g_topk[2 * t] = i0;
        g_topk[2 * t + 1] = i1;
        atomicAdd(&g_cnt[i0], 1);
        atomicAdd(&g_cnt[i1], 1);
    }
}

__global__ void offsets_k() {
    if (threadIdx.x == 0) {
        int a = 0;
        for (int e = 0; e < NEXP; e++) { g_off[e] = a; a += g_cnt[e]; }
    }
}

__global__ void fill_k() {
    int t = blockIdx.x * blockDim.x + threadIdx.x;
    if (t >= TOK) return;
    for (int k2 = 0; k2 < 2; k2++) {
        int e = g_topk[2 * t + k2];
        int pos = g_off[e] + atomicAdd(&g_fill[e], 1);
        g_perm[pos] = t;
        g_slot[2 * t + k2] = pos;
    }
}

__global__ void silu_k() {
    int i = blockIdx.x * blockDim.x + threadIdx.x;
    if (i >= SLOTS * HID) return;
    float g = g_gbuf[i], u = g_ubuf[i];
    g_gbuf[i] = g / (1.f + expf(-g)) * u;
}

__global__ void epi_k(float* __restrict__ out) {
    int i = blockIdx.x * blockDim.x + threadIdx.x;
    if (i >= TOK * DIM) return;
    int t = i >> 10, d = i & 1023;
    float r = g_x1[i];
    r += g_cw[2 * t] * g_dbuf[(size_t)g_slot[2 * t] * DIM + d];
    r += g_cw[2 * t + 1] * g_dbuf[(size_t)g_slot[2 * t + 1] * DIM + d];
    out[i] = r;
}

__global__ void fin_k(float* __restrict__ out) {
    if (threadIdx.x == 0 && blockIdx.x == 0) {
        float s = 0.f;
        for (int e = 0; e < NEXP; e++) {
            float d = g_dist[e] * (1.f / 2048.f);
            out[TOK * DIM + 1 + e] = d;
            s += d * d;
        }
        out[TOK * DIM] = 8.f * s;
    }
}

// ------------------------- launch -------------------------
extern "C" void kernel_launch(void* const* d_in, const int* in_sizes, int n_in,
                              void* d_out, int out_size) {
    const float* x    = (const float*)d_in[0];
    const float* ln1g = (const float*)d_in[1];
    const float* ln1b = (const float*)d_in[2];
    const float* ln2g = (const float*)d_in[3];
    const float* ln2b = (const float*)d_in[4];
    const float* wqkv = (const float*)d_in[5];
    const float* wo   = (const float*)d_in[6];
    const float* gw   = (const float*)d_in[7];
    const float* wg   = (const float*)d_in[8];
    const float* wu   = (const float*)d_in[9];
    const float* wd   = (const float*)d_in[10];
    float* out = (float*)d_out;

    float *pxn1, *pqkv, *pattn, *px1, *pxn2, *pg, *pu, *pd;
    cudaGetSymbolAddress((void**)&pxn1, g_xn1);
    cudaGetSymbolAddress((void**)&pqkv, g_qkv);
    cudaGetSymbolAddress((void**)&pattn, g_attn);
    cudaGetSymbolAddress((void**)&px1, g_x1);
    cudaGetSymbolAddress((void**)&pxn2, g_xn2);
    cudaGetSymbolAddress((void**)&pg, g_gbuf);
    cudaGetSymbolAddress((void**)&pu, g_ubuf);
    cudaGetSymbolAddress((void**)&pd, g_dbuf);

    cudaFuncSetAttribute(attn_k, cudaFuncAttributeMaxDynamicSharedMemorySize, 4 * 64 * 65 * 4);

    zero_k<<<1, 32>>>();
    ln_k<<<TOK, 256>>>(x, ln1g, ln1b, pxn1);
    sgemm_k<<<dim3(TDIM / 128, TOK / 128), 256>>>(pxn1, wqkv, pqkv, nullptr,
                                                  TOK, TDIM, DIM, DIM, TDIM, TDIM, 0);
    rope_k<<<(TOK * NHEAD * 32 + 255) / 256, 256>>>(pqkv);
    attn_k<<<dim3(SEQ / 64, 4 * NHEAD), 256, 4 * 64 * 65 * 4>>>(pqkv, pattn);
    sgemm_k<<<dim3(DIM / 128, TOK / 128), 256>>>(pattn, wo, px1, x,
                                                 TOK, DIM, DIM, DIM, DIM, DIM, DIM);
    ln_k<<<TOK, 256>>>(px1, ln2g, ln2b, pxn2);
    gate_k<<<TOK, 256>>>(pxn2, gw);
    offsets_k<<<1, 1>>>();
    fill_k<<<(TOK + 255) / 256, 256>>>();
    moe_gemm_gather_k<<<dim3(HID / 128, 32, NEXP), 256>>>(pxn2, wg, pg, DIM, HID);
    moe_gemm_gather_k<<<dim3(HID / 128, 32, NEXP), 256>>>(pxn2, wu, pu, DIM, HID);
    silu_k<<<(SLOTS * HID + 255) / 256, 256>>>();
    moe_gemm_dense_k<<<dim3(DIM / 128, 32, NEXP), 256>>>(pg, wd, pd, HID, DIM);
    epi_k<<<(TOK * DIM + 255) / 256, 256>>>(out);
    fin_k<<<1, 1>>>(out);
}

// round 5
// speedup vs baseline: 3.1245x; 3.1245x over previous
#include <cuda_runtime.h>
#include <cuda_bf16.h>
#include <math.h>

#define TOK 2048
#define DIM 1024
#define TDIM 3072
#define SEQ 512
#define NHEAD 16
#define HDIM 64
#define NEXP 8
#define HID 1792
#define SLOTS 4096

// ------------------------- scratch (device globals) -------------------------
__device__ float g_xn1[TOK * DIM];
__device__ float g_qkv[TOK * TDIM];
__device__ float g_attn[TOK * DIM];
__device__ float g_x1[TOK * DIM];
__device__ float g_xn2[TOK * DIM];
__device__ float g_gbuf[SLOTS * HID];
__device__ float g_ubuf[SLOTS * HID];
__device__ float g_dbuf[SLOTS * DIM];
__device__ float g_cw[TOK * 2];
__device__ int   g_topk[TOK * 2];
__device__ int   g_slot[TOK * 2];
__device__ int   g_perm[SLOTS];
__device__ int   g_cnt[NEXP];
__device__ int   g_off[NEXP];
__device__ int   g_fill[NEXP];
__device__ float g_dist[NEXP];
__device__ float g_cs[SEQ * 32 * 2];   // rope cos/sin table

// ------------------------- small helpers -------------------------
__device__ __forceinline__ float block_sum(float v) {
    __shared__ float red[8];
    #pragma unroll
    for (int o = 16; o; o >>= 1) v += __shfl_xor_sync(0xffffffffu, v, o);
    int w = threadIdx.x >> 5;
    if ((threadIdx.x & 31) == 0) red[w] = v;
    __syncthreads();
    if (threadIdx.x < 32) {
        float t = (threadIdx.x < 8) ? red[threadIdx.x] : 0.f;
        #pragma unroll
        for (int o = 4; o; o >>= 1) t += __shfl_xor_sync(0xffffffffu, t, o);
        if (threadIdx.x == 0) red[0] = t;
    }
    __syncthreads();
    float r = red[0];
    __syncthreads();
    return r;
}

__device__ __forceinline__ unsigned f2tf32(float x) {
    unsigned r;
    asm("cvt.rna.tf32.f32 %0, %1;" : "=r"(r) : "f"(x));
    return r;
}

// ------------------------- LayerNorm -------------------------
__global__ void ln_k(const float* __restrict__ x, const float* __restrict__ g,
                     const float* __restrict__ b, float* __restrict__ y) {
    int row = blockIdx.x;
    int tid = threadIdx.x;
    const float* xr = x + (size_t)row * DIM;
    float v[4];
    float s = 0.f;
    #pragma unroll
    for (int i = 0; i < 4; i++) { v[i] = xr[tid + 256 * i]; s += v[i]; }
    float mu = block_sum(s) * (1.f / 1024.f);
    float q = 0.f;
    #pragma unroll
    for (int i = 0; i < 4; i++) { float d = v[i] - mu; q += d * d; }
    float var = block_sum(q) * (1.f / 1024.f);
    float rs = rsqrtf(var + 1e-5f);
    float* yr = y + (size_t)row * DIM;
    #pragma unroll
    for (int i = 0; i < 4; i++) {
        int c = tid + 256 * i;
        yr[c] = (v[i] - mu) * rs * g[c] + b[c];
    }
}

// ------------------------- generic 128x128 SGEMM body (fp32, pre-routing path) -------------------------
__device__ __forceinline__ void gemm_body(
    const float* __restrict__ A, int lda,
    const float* __restrict__ B, int ldb,
    float* __restrict__ C, int ldc,
    const float* __restrict__ R, int ldr,
    int M, int N, int K, int bm, int bn) {
    __shared__ float As[8][128];
    __shared__ float Bs[8][128];
    const int tid = threadIdx.x;
    const int arow = tid >> 1;
    const int acol = (tid & 1) << 2;
    const int brow = tid >> 5;
    const int bcol = (tid & 31) << 2;
    const int grow = bm * 128 + arow;
    const bool aval = grow < M;
    const float* Ap = A + (size_t)(aval ? grow : 0) * lda + acol;
    const float* Bp = B + (size_t)brow * ldb + bn * 128 + bcol;
    const int rb = (tid >> 4) << 3;
    const int cb = (tid & 15) << 3;
    float acc[8][8];
    #pragma unroll
    for (int i = 0; i < 8; i++)
        #pragma unroll
        for (int j = 0; j < 8; j++) acc[i][j] = 0.f;

    for (int kt = 0; kt < K; kt += 8) {
        float4 av = aval ? *(const float4*)(Ap + kt) : make_float4(0.f, 0.f, 0.f, 0.f);
        As[acol + 0][arow] = av.x;
        As[acol + 1][arow] = av.y;
        As[acol + 2][arow] = av.z;
        As[acol + 3][arow] = av.w;
        *(float4*)&Bs[brow][bcol] = *(const float4*)(Bp + (size_t)kt * ldb);
        __syncthreads();
        #pragma unroll
        for (int k = 0; k < 8; k++) {
            float a[8], b[8];
            #pragma unroll
            for (int i = 0; i < 8; i++) a[i] = As[k][rb + i];
            #pragma unroll
            for (int j = 0; j < 8; j++) b[j] = Bs[k][cb + j];
            #pragma unroll
            for (int i = 0; i < 8; i++)
                #pragma unroll
                for (int j = 0; j < 8; j++)
                    acc[i][j] = fmaf(a[i], b[j], acc[i][j]);
        }
        __syncthreads();
    }
    #pragma unroll
    for (int i = 0; i < 8; i++) {
        int row = bm * 128 + rb + i;
        if (row < M) {
            float* Cp = C + (size_t)row * ldc + bn * 128 + cb;
            if (R) {
                const float* Rp = R + (size_t)row * ldr + bn * 128 + cb;
                #pragma unroll
                for (int j = 0; j < 8; j++) Cp[j] = acc[i][j] + Rp[j];
            } else {
                #pragma unroll
                for (int j = 0; j < 8; j++) Cp[j] = acc[i][j];
            }
        }
    }
}

__global__ void sgemm_k(const float* __restrict__ A, const float* __restrict__ B,
                        float* __restrict__ C, const float* __restrict__ R,
                        int M, int N, int K, int lda, int ldb, int ldc, int ldr) {
    gemm_body(A, lda, B, ldb, C, ldc, R, ldr, M, N, K, blockIdx.y, blockIdx.x);
}

// ------------------------- MoE grouped GEMM, TF32 tensor cores -------------------------
// C[off+m][n] = sum_k A_row(m)[k] * W_e[k][n]
// gather=1: A_row(m) = X[perm[off+m]]; gather=0: A_row(m) = X[off+m]
// Tile: 128(M) x 128(N) x 16(K). 8 warps, each 32x64 via m16n8k8.
__global__ void __launch_bounds__(256, 2)
moe_mma_k(const float* __restrict__ X, const float* __restrict__ W,
          float* __restrict__ Cb, int K, int N, int gather) {
    const int e = blockIdx.z;
    const int cnt = g_cnt[e];
    const int bm = blockIdx.y;
    if (bm * 128 >= cnt) return;
    const int off = g_off[e];
    const int bn = blockIdx.x;
    const float* B = W + (size_t)e * K * N;
    float* C = Cb + (size_t)off * N;

    __shared__ float As[2][16][136];
    __shared__ float Bs[2][16][136];

    const int tid = threadIdx.x;
    const int warp = tid >> 5, lane = tid & 31;
    const int g = lane >> 2, t = lane & 3;
    const int wm = (warp & 3) * 32;
    const int wn = (warp >> 2) * 64;

    // A-load assignment: 2 tasks/thread, task -> (row, kquad)
    int amrow[2]; const float* aptr[2]; bool avalid[2];
    int akq[2];
    #pragma unroll
    for (int i = 0; i < 2; i++) {
        int task = tid + 256 * i;
        int mr = task >> 2;
        akq[i] = (task & 3) * 4;
        amrow[i] = mr;
        avalid[i] = (bm * 128 + mr) < cnt;
        int slot = off + bm * 128 + (avalid[i] ? mr : 0);
        int arow = gather ? g_perm[slot] : slot;
        aptr[i] = X + (size_t)arow * K + akq[i];
    }
    // B-load assignment
    int bkr[2], bnq[2]; const float* bptr[2];
    #pragma unroll
    for (int i = 0; i < 2; i++) {
        int task = tid + 256 * i;
        bkr[i] = task >> 5;
        bnq[i] = (task & 31) * 4;
        bptr[i] = B + (size_t)bkr[i] * N + bn * 128 + bnq[i];
    }

    float c[2][8][4];
    #pragma unroll
    for (int im = 0; im < 2; im++)
        #pragma unroll
        for (int jn = 0; jn < 8; jn++)
            #pragma unroll
            for (int q = 0; q < 4; q++) c[im][jn][q] = 0.f;

    const int ntiles = K / 16;

    // preload tile 0
    #pragma unroll
    for (int i = 0; i < 2; i++) {
        float4 av = avalid[i] ? *(const float4*)(aptr[i]) : make_float4(0, 0, 0, 0);
        As[0][akq[i] + 0][amrow[i]] = __uint_as_float(f2tf32(av.x));
        As[0][akq[i] + 1][amrow[i]] = __uint_as_float(f2tf32(av.y));
        As[0][akq[i] + 2][amrow[i]] = __uint_as_float(f2tf32(av.z));
        As[0][akq[i] + 3][amrow[i]] = __uint_as_float(f2tf32(av.w));
        float4 bv = *(const float4*)(bptr[i]);
        Bs[0][bkr[i]][bnq[i] + 0] = __uint_as_float(f2tf32(bv.x));
        Bs[0][bkr[i]][bnq[i] + 1] = __uint_as_float(f2tf32(bv.y));
        Bs[0][bkr[i]][bnq[i] + 2] = __uint_as_float(f2tf32(bv.z));
        Bs[0][bkr[i]][bnq[i] + 3] = __uint_as_float(f2tf32(bv.w));
    }
    __syncthreads();

    int cur = 0;
    for (int kt = 0; kt < ntiles; kt++) {
        // prefetch next tile into registers
        float4 pa[2], pb[2];
        bool have_next = (kt + 1) < ntiles;
        if (have_next) {
            #pragma unroll
            for (int i = 0; i < 2; i++) {
                pa[i] = avalid[i] ? *(const float4*)(aptr[i] + (kt + 1) * 16)
                                  : make_float4(0, 0, 0, 0);
                pb[i] = *(const float4*)(bptr[i] + (size_t)(kt + 1) * 16 * N);
            }
        }
        // compute on cur
        #pragma unroll
        for (int ks = 0; ks < 16; ks += 8) {
            unsigned a0[2], a1[2], a2[2], a3[2];
            #pragma unroll
            for (int im = 0; im < 2; im++) {
                a0[im] = __float_as_uint(As[cur][ks + t][wm + im * 16 + g]);
                a1[im] = __float_as_uint(As[cur][ks + t][wm + im * 16 + 8 + g]);
                a2[im] = __float_as_uint(As[cur][ks + t + 4][wm + im * 16 + g]);
                a3[im] = __float_as_uint(As[cur][ks + t + 4][wm + im * 16 + 8 + g]);
            }
            #pragma unroll
            for (int jn = 0; jn < 8; jn++) {
                unsigned b0 = __float_as_uint(Bs[cur][ks + t][wn + jn * 8 + g]);
                unsigned b1 = __float_as_uint(Bs[cur][ks + t + 4][wn + jn * 8 + g]);
                #pragma unroll
                for (int im = 0; im < 2; im++) {
                    asm volatile(
                        "mma.sync.aligned.m16n8k8.row.col.f32.tf32.tf32.f32 "
                        "{%0,%1,%2,%3}, {%4,%5,%6,%7}, {%8,%9}, {%0,%1,%2,%3};"
                        : "+f"(c[im][jn][0]), "+f"(c[im][jn][1]),
                          "+f"(c[im][jn][2]), "+f"(c[im][jn][3])
                        : "r"(a0[im]), "r"(a1[im]), "r"(a2[im]), "r"(a3[im]),
                          "r"(b0), "r"(b1));
                }
            }
        }
        if (have_next) {
            int nxt = cur ^ 1;
            #pragma unroll
            for (int i = 0; i < 2; i++) {
                As[nxt][akq[i] + 0][amrow[i]] = __uint_as_float(f2tf32(pa[i].x));
                As[nxt][akq[i] + 1][amrow[i]] = __uint_as_float(f2tf32(pa[i].y));
                As[nxt][akq[i] + 2][amrow[i]] = __uint_as_float(f2tf32(pa[i].z));
                As[nxt][akq[i] + 3][amrow[i]] = __uint_as_float(f2tf32(pa[i].w));
                Bs[nxt][bkr[i]][bnq[i] + 0] = __uint_as_float(f2tf32(pb[i].x));
                Bs[nxt][bkr[i]][bnq[i] + 1] = __uint_as_float(f2tf32(pb[i].y));
                Bs[nxt][bkr[i]][bnq[i] + 2] = __uint_as_float(f2tf32(pb[i].z));
                Bs[nxt][bkr[i]][bnq[i] + 3] = __uint_as_float(f2tf32(pb[i].w));
            }
            __syncthreads();
            cur = nxt;
        }
    }

    // epilogue
    #pragma unroll
    for (int im = 0; im < 2; im++) {
        #pragma unroll
        for (int half = 0; half < 2; half++) {
            int rowl = bm * 128 + wm + im * 16 + g + half * 8;
            if (rowl < cnt) {
                float* Cp = C + (size_t)rowl * N + bn * 128 + wn;
                #pragma unroll
                for (int jn = 0; jn < 8; jn++) {
                    Cp[jn * 8 + 2 * t]     = c[im][jn][half * 2 + 0];
                    Cp[jn * 8 + 2 * t + 1] = c[im][jn][half * 2 + 1];
                }
            }
        }
    }
}

// ------------------------- RoPE -------------------------
__global__ void rope_tab_k() {
    int idx = blockIdx.x * blockDim.x + threadIdx.x;
    if (idx >= SEQ * 32) return;
    int s = idx >> 5, i = idx & 31;
    double invd = pow(10000.0, -(double)(2 * i) / 64.0);
    float f = (float)s * (float)invd;     // matches reference fp32 outer product
    g_cs[2 * idx]     = (float)cos((double)f);
    g_cs[2 * idx + 1] = (float)sin((double)f);
}

__global__ void rope_k(float* __restrict__ qkv) {
    int idx = blockIdx.x * blockDim.x + threadIdx.x;
    if (idx >= TOK * NHEAD * 32) return;
    int i = idx & 31;
    int h = (idx >> 5) & 15;
    int row = idx >> 9;
    int s = row & (SEQ - 1);
    float2 cs = *(const float2*)&g_cs[2 * (s * 32 + i)];
    float c = cs.x, sn = cs.y;
    float* qp = qkv + (size_t)row * TDIM + h * 64 + 2 * i;
    float xe = qp[0], xo = qp[1];
    qp[0] = xe * c - xo * sn;
    qp[1] = xe * sn + xo * c;
    float* kp = qp + DIM;
    xe = kp[0]; xo = kp[1];
    kp[0] = xe * c - xo * sn;
    kp[1] = xe * sn + xo * c;
}

// ------------------------- flash attention (64x64 tiles, hd=64) -------------------------
__global__ void attn_k(const float* __restrict__ qkv, float* __restrict__ out) {
    extern __shared__ float sm[];
    float* Qs = sm;                 // 64 x 65
    float* Ks = sm + 64 * 65;
    float* Vs = sm + 2 * 64 * 65;
    float* Ps = sm + 3 * 64 * 65;
    int mt = blockIdx.x;
    int b = blockIdx.y >> 4, h = blockIdx.y & 15;
    int tid = threadIdx.x;
    int ty = tid >> 4, tx = tid & 15;
    const size_t rowbase = (size_t)(b * SEQ) * TDIM;

    for (int i = tid; i < 64 * 64; i += 256) {
        int r = i >> 6, c = i & 63;
        Qs[r * 65 + c] = qkv[rowbase + (size_t)(mt * 64 + r) * TDIM + h * 64 + c];
    }
    float m_i[4], l_i[4], o[4][4];
    #pragma unroll
    for (int i = 0; i < 4; i++) {
        m_i[i] = -INFINITY; l_i[i] = 0.f;
        #pragma unroll
        for (int j = 0; j < 4; j++) o[i][j] = 0.f;
    }

    for (int nt = 0; nt <= mt; nt++) {
        __syncthreads();
        for (int i = tid; i < 64 * 64; i += 256) {
            int r = i >> 6, c = i & 63;
            size_t base = rowbase + (size_t)(nt * 64 + r) * TDIM + h * 64 + c;
            Ks[r * 65 + c] = qkv[base + DIM];
            Vs[r * 65 + c] = qkv[base + 2 * DIM];
        }
        __syncthreads();

        float s4[4][4];
        #pragma unroll
        for (int i = 0; i < 4; i++)
            #pragma unroll
            for (int j = 0; j < 4; j++) s4[i][j] = 0.f;
        #pragma unroll 8
        for (int d = 0; d < 64; d++) {
            float a[4], k4[4];
            #pragma unroll
            for (int i = 0; i < 4; i++) a[i] = Qs[(ty * 4 + i) * 65 + d];
            #pragma unroll
            for (int j = 0; j < 4; j++) k4[j] = Ks[(tx * 4 + j) * 65 + d];
            #pragma unroll
            for (int i = 0; i < 4; i++)
                #pragma unroll
                for (int j = 0; j < 4; j++)
                    s4[i][j] = fmaf(a[i], k4[j], s4[i][j]);
        }
        const float scale = 0.125f;
        #pragma unroll
        for (int i = 0; i < 4; i++) {
            #pragma unroll
            for (int j = 0; j < 4; j++) {
                float v = s4[i][j] * scale;
                if (nt == mt && (tx * 4 + j) > (ty * 4 + i)) v = -INFINITY;
                s4[i][j] = v;
            }
            float mx = fmaxf(fmaxf(s4[i][0], s4[i][1]), fmaxf(s4[i][2], s4[i][3]));
            #pragma unroll
            for (int o2 = 8; o2; o2 >>= 1) mx = fmaxf(mx, __shfl_xor_sync(0xffffffffu, mx, o2, 16));
            float mn = fmaxf(m_i[i], mx);
            float alpha = expf(m_i[i] - mn);
            float rsum = 0.f;
            #pragma unroll
            for (int j = 0; j < 4; j++) {
                float p = expf(s4[i][j] - mn);
                Ps[(ty * 4 + i) * 65 + tx * 4 + j] = p;
                rsum += p;
            }
            #pragma unroll
            for (int o2 = 8; o2; o2 >>= 1) rsum += __shfl_xor_sync(0xffffffffu, rsum, o2, 16);
            l_i[i] = l_i[i] * alpha + rsum;
            m_i[i] = mn;
            #pragma unroll
            for (int j = 0; j < 4; j++) o[i][j] *= alpha;
        }
        __syncthreads();
        #pragma unroll 8
        for (int n = 0; n < 64; n++) {
            float p4[4], v4[4];
            #pragma unroll
            for (int i = 0; i < 4; i++) p4[i] = Ps[(ty * 4 + i) * 65 + n];
            #pragma unroll
            for (int j = 0; j < 4; j++) v4[j] = Vs[n * 65 + tx * 4 + j];
            #pragma unroll
            for (int i = 0; i < 4; i++)
                #pragma unroll
                for (int j = 0; j < 4; j++)
                    o[i][j] = fmaf(p4[i], v4[j], o[i][j]);
        }
    }
    #pragma unroll
    for (int i = 0; i < 4; i++) {
        float inv = 1.f / l_i[i];
        #pragma unroll
        for (int j = 0; j < 4; j++)
            out[(size_t)(b * SEQ + mt * 64 + ty * 4 + i) * DIM + h * 64 + tx * 4 + j] = o[i][j] * inv;
    }
}

// ------------------------- MoE gate / routing -------------------------
__global__ void zero_k() {
    int t = threadIdx.x;
    if (t < NEXP) { g_cnt[t] = 0; g_fill[t] = 0; g_dist[t] = 0.f; }
}

__global__ void gate_k(const float* __restrict__ xn2, const float* __restrict__ gw) {
    int t = blockIdx.x;
    int wid = threadIdx.x >> 5, lane = threadIdx.x & 31;
    const float* xr = xn2 + (size_t)t * DIM;
    float acc = 0.f;
    for (int k = lane; k < DIM; k += 32) {
        float a = __bfloat162float(__float2bfloat16(xr[k]));
        float w = __bfloat162float(__float2bfloat16(gw[(size_t)k * NEXP + wid]));
        acc = fmaf(a, w, acc);
    }
    #pragma unroll
    for (int o = 16; o; o >>= 1) acc += __shfl_xor_sync(0xffffffffu, acc, o);
    __shared__ float lg[NEXP];
    if (lane == 0) lg[wid] = __bfloat162float(__float2bfloat16(acc));  // bf16 result like jax
    __syncthreads();
    if (threadIdx.x == 0) {
        float mx = lg[0];
        for (int e = 1; e < NEXP; e++) mx = fmaxf(mx, lg[e]);
        float p[NEXP], sum = 0.f;
        for (int e = 0; e < NEXP; e++) { p[e] = expf(lg[e] - mx); sum += p[e]; }
        float inv = 1.f / sum;
        for (int e = 0; e < NEXP; e++) atomicAdd(&g_dist[e], p[e] * inv);
        int i0 = 0;
        for (int e = 1; e < NEXP; e++) if (lg[e] > lg[i0]) i0 = e;
        int i1 = -1;
        for (int e = 0; e < NEXP; e++) {
            if (e == i0) continue;
            if (i1 < 0 || lg[e] > lg[i1]) i1 = e;
        }
        float eb = expf(lg[i1] - lg[i0]);
        float w0 = 1.f / (1.f + eb);
        g_cw[2 * t] = w0;
        g_cw[2 * t + 1] = eb * w0;
        g_topk[2 * t] = i0;
        g_topk[2 * t + 1] = i1;
        atomicAdd(&g_cnt[i0], 1);
        atomicAdd(&g_cnt[i1], 1);
    }
}

__global__ void offsets_k() {
    if (threadIdx.x == 0) {
        int a = 0;
        for (int e = 0; e < NEXP; e++) { g_off[e] = a; a += g_cnt[e]; }
    }
}

__global__ void fill_k() {
    int t = blockIdx.x * blockDim.x + threadIdx.x;
    if (t >= TOK) return;
    for (int k2 = 0; k2 < 2; k2++) {
        int e = g_topk[2 * t + k2];
        int pos = g_off[e] + atomicAdd(&g_fill[e], 1);
        g_perm[pos] = t;
        g_slot[2 * t + k2] = pos;
    }
}

__global__ void silu_k() {
    int i = blockIdx.x * blockDim.x + threadIdx.x;
    if (i >= SLOTS * HID) return;
    float g = g_gbuf[i], u = g_ubuf[i];
    g_gbuf[i] = g / (1.f + expf(-g)) * u;
}

__global__ void epi_k(float* __restrict__ out) {
    int i = blockIdx.x * blockDim.x + threadIdx.x;
    if (i >= TOK * DIM) return;
    int t = i >> 10, d = i & 1023;
    float r = g_x1[i];
    r += g_cw[2 * t] * g_dbuf[(size_t)g_slot[2 * t] * DIM + d];
    r += g_cw[2 * t + 1] * g_dbuf[(size_t)g_slot[2 * t + 1] * DIM + d];
    out[i] = r;
}

__global__ void fin_k(float* __restrict__ out) {
    if (threadIdx.x == 0 && blockIdx.x == 0) {
        float s = 0.f;
        for (int e = 0; e < NEXP; e++) {
            float d = g_dist[e] * (1.f / 2048.f);
            out[TOK * DIM + 1 + e] = d;
            s += d * d;
        }
        out[TOK * DIM] = 8.f * s;
    }
}

// ------------------------- launch -------------------------
extern "C" void kernel_launch(void* const* d_in, const int* in_sizes, int n_in,
                              void* d_out, int out_size) {
    const float* x    = (const float*)d_in[0];
    const float* ln1g = (const float*)d_in[1];
    const float* ln1b = (const float*)d_in[2];
    const float* ln2g = (const float*)d_in[3];
    const float* ln2b = (const float*)d_in[4];
    const float* wqkv = (const float*)d_in[5];
    const float* wo   = (const float*)d_in[6];
    const float* gw   = (const float*)d_in[7];
    const float* wg   = (const float*)d_in[8];
    const float* wu   = (const float*)d_in[9];
    const float* wd   = (const float*)d_in[10];
    float* out = (float*)d_out;

    float *pxn1, *pqkv, *pattn, *px1, *pxn2, *pg, *pu, *pd;
    cudaGetSymbolAddress((void**)&pxn1, g_xn1);
    cudaGetSymbolAddress((void**)&pqkv, g_qkv);
    cudaGetSymbolAddress((void**)&pattn, g_attn);
    cudaGetSymbolAddress((void**)&px1, g_x1);
    cudaGetSymbolAddress((void**)&pxn2, g_xn2);
    cudaGetSymbolAddress((void**)&pg, g_gbuf);
    cudaGetSymbolAddress((void**)&pu, g_ubuf);
    cudaGetSymbolAddress((void**)&pd, g_dbuf);

    cudaFuncSetAttribute(attn_k, cudaFuncAttributeMaxDynamicSharedMemorySize, 4 * 64 * 65 * 4);

    zero_k<<<1, 32>>>();
    rope_tab_k<<<(SEQ * 32 + 255) / 256, 256>>>();
    ln_k<<<TOK, 256>>>(x, ln1g, ln1b, pxn1);
    sgemm_k<<<dim3(TDIM / 128, TOK / 128), 256>>>(pxn1, wqkv, pqkv, nullptr,
                                                  TOK, TDIM, DIM, DIM, TDIM, TDIM, 0);
    rope_k<<<(TOK * NHEAD * 32 + 255) / 256, 256>>>(pqkv);
    attn_k<<<dim3(SEQ / 64, 4 * NHEAD), 256, 4 * 64 * 65 * 4>>>(pqkv, pattn);
    sgemm_k<<<dim3(DIM / 128, TOK / 128), 256>>>(pattn, wo, px1, x,
                                                 TOK, DIM, DIM, DIM, DIM, DIM, DIM);
    ln_k<<<TOK, 256>>>(px1, ln2g, ln2b, pxn2);
    gate_k<<<TOK, 256>>>(pxn2, gw);
    offsets_k<<<1, 1>>>();
    fill_k<<<(TOK + 255) / 256, 256>>>();
    moe_mma_k<<<dim3(HID / 128, 32, NEXP), 256>>>(pxn2, wg, pg, DIM, HID, 1);
    moe_mma_k<<<dim3(HID / 128, 32, NEXP), 256>>>(pxn2, wu, pu, DIM, HID, 1);
    silu_k<<<(SLOTS * HID + 255) / 256, 256>>>();
    moe_mma_k<<<dim3(DIM / 128, 32, NEXP), 256>>>(pg, wd, pd, HID, DIM, 0);
    epi_k<<<(TOK * DIM + 255) / 256, 256>>>(out);
    fin_k<<<1, 1>>>(out);
}

// round 8
// speedup vs baseline: 3.5705x; 1.1428x over previous
#include <cuda_runtime.h>
#include <cuda_bf16.h>
#include <math.h>

#define TOK 2048
#define DIM 1024
#define TDIM 3072
#define SEQ 512
#define NHEAD 16
#define HDIM 64
#define NEXP 8
#define HID 1792
#define SLOTS 4096

// ------------------------- scratch (device globals) -------------------------
__device__ float g_xn1[TOK * DIM];
__device__ float g_qkv[TOK * TDIM];
__device__ float g_attn[TOK * DIM];
__device__ float g_x1[TOK * DIM];
__device__ float g_xn2[TOK * DIM];
__device__ float g_gbuf[SLOTS * HID];
__device__ float g_ubuf[SLOTS * HID];
__device__ float g_dbuf[SLOTS * DIM];
__device__ float g_cw[TOK * 2];
__device__ int   g_topk[TOK * 2];
__device__ int   g_slot[TOK * 2];
__device__ int   g_perm[SLOTS];
__device__ int   g_cnt[NEXP];
__device__ int   g_off[NEXP];
__device__ int   g_fill[NEXP];
__device__ float g_dist[NEXP];
__device__ float g_cs[SEQ * 32 * 2];   // rope cos/sin table

// ------------------------- small helpers -------------------------
__device__ __forceinline__ float block_sum(float v) {
    __shared__ float red[8];
    #pragma unroll
    for (int o = 16; o; o >>= 1) v += __shfl_xor_sync(0xffffffffu, v, o);
    int w = threadIdx.x >> 5;
    if ((threadIdx.x & 31) == 0) red[w] = v;
    __syncthreads();
    if (threadIdx.x < 32) {
        float t = (threadIdx.x < 8) ? red[threadIdx.x] : 0.f;
        #pragma unroll
        for (int o = 4; o; o >>= 1) t += __shfl_xor_sync(0xffffffffu, t, o);
        if (threadIdx.x == 0) red[0] = t;
    }
    __syncthreads();
    float r = red[0];
    __syncthreads();
    return r;
}

__device__ __forceinline__ unsigned f2tf32(float x) {
    unsigned r;
    asm("cvt.rna.tf32.f32 %0, %1;" : "=r"(r) : "f"(x));
    return r;
}

__device__ __forceinline__ void mma_tf32(float* c, unsigned a0, unsigned a1,
                                         unsigned a2, unsigned a3,
                                         unsigned b0, unsigned b1) {
    asm volatile(
        "mma.sync.aligned.m16n8k8.row.col.f32.tf32.tf32.f32 "
        "{%0,%1,%2,%3}, {%4,%5,%6,%7}, {%8,%9}, {%0,%1,%2,%3};"
        : "+f"(c[0]), "+f"(c[1]), "+f"(c[2]), "+f"(c[3])
        : "r"(a0), "r"(a1), "r"(a2), "r"(a3), "r"(b0), "r"(b1));
}

// ------------------------- LayerNorm -------------------------
__global__ void ln_k(const float* __restrict__ x, const float* __restrict__ g,
                     const float* __restrict__ b, float* __restrict__ y) {
    int row = blockIdx.x;
    int tid = threadIdx.x;
    const float* xr = x + (size_t)row * DIM;
    float v[4];
    float s = 0.f;
    #pragma unroll
    for (int i = 0; i < 4; i++) { v[i] = xr[tid + 256 * i]; s += v[i]; }
    float mu = block_sum(s) * (1.f / 1024.f);
    float q = 0.f;
    #pragma unroll
    for (int i = 0; i < 4; i++) { float d = v[i] - mu; q += d * d; }
    float var = block_sum(q) * (1.f / 1024.f);
    float rs = rsqrtf(var + 1e-5f);
    float* yr = y + (size_t)row * DIM;
    #pragma unroll
    for (int i = 0; i < 4; i++) {
        int c = tid + 256 * i;
        yr[c] = (v[i] - mu) * rs * g[c] + b[c];
    }
}

// ------------------------- dense 3xTF32 GEMM (fp32-accurate, pre-routing path) -------------------------
// C[m][n] = sum_k A[m][k] * B[k][n]  (+ R[m][n] if R)
// M = multiple of 128 (rows fully covered by grid.y), N mult of 128, K mult of 16.
__global__ void __launch_bounds__(256, 2)
gemm3x_k(const float* __restrict__ A, const float* __restrict__ B,
         float* __restrict__ C, const float* __restrict__ R, int N, int K) {
    const int bn = blockIdx.x, bm = blockIdx.y;
    __shared__ float Ah[16][136], Al[16][136], Bh[16][136], Bl[16][136];

    const int tid = threadIdx.x;
    const int warp = tid >> 5, lane = tid & 31;
    const int g = lane >> 2, t = lane & 3;
    const int wm = (warp & 3) * 32;
    const int wn = (warp >> 2) * 64;

    int amrow[2], akq[2], bkr[2], bnq[2];
    const float* aptr[2];
    const float* bptr[2];
    #pragma unroll
    for (int i = 0; i < 2; i++) {
        int task = tid + 256 * i;
        amrow[i] = task >> 2;
        akq[i] = (task & 3) * 4;
        aptr[i] = A + (size_t)(bm * 128 + amrow[i]) * K + akq[i];
        bkr[i] = task >> 5;
        bnq[i] = (task & 31) * 4;
        bptr[i] = B + (size_t)bkr[i] * N + bn * 128 + bnq[i];
    }

    float c[2][8][4];
    #pragma unroll
    for (int im = 0; im < 2; im++)
        #pragma unroll
        for (int jn = 0; jn < 8; jn++)
            #pragma unroll
            for (int q = 0; q < 4; q++) c[im][jn][q] = 0.f;

    float4 pa[2], pb[2];
    #pragma unroll
    for (int i = 0; i < 2; i++) {
        pa[i] = *(const float4*)(aptr[i]);
        pb[i] = *(const float4*)(bptr[i]);
    }
    // store tile 0 (hi/lo split)
    #pragma unroll
    for (int i = 0; i < 2; i++) {
        float av[4] = {pa[i].x, pa[i].y, pa[i].z, pa[i].w};
        float bv[4] = {pb[i].x, pb[i].y, pb[i].z, pb[i].w};
        #pragma unroll
        for (int q = 0; q < 4; q++) {
            unsigned h = f2tf32(av[q]);
            Ah[akq[i] + q][amrow[i]] = __uint_as_float(h);
            Al[akq[i] + q][amrow[i]] =
                __uint_as_float(f2tf32(av[q] - __uint_as_float(h)));
            unsigned hb = f2tf32(bv[q]);
            Bh[bkr[i]][bnq[i] + q] = __uint_as_float(hb);
            Bl[bkr[i]][bnq[i] + q] =
                __uint_as_float(f2tf32(bv[q] - __uint_as_float(hb)));
        }
    }
    __syncthreads();

    const int ntiles = K / 16;
    for (int kt = 0; kt < ntiles; kt++) {
        const bool have_next = (kt + 1) < ntiles;
        if (have_next) {
            #pragma unroll
            for (int i = 0; i < 2; i++) {
                pa[i] = *(const float4*)(aptr[i] + (kt + 1) * 16);
                pb[i] = *(const float4*)(bptr[i] + (size_t)(kt + 1) * 16 * N);
            }
        }
        #pragma unroll
        for (int ks = 0; ks < 16; ks += 8) {
            unsigned ah[2][4], al[2][4];
            #pragma unroll
            for (int im = 0; im < 2; im++) {
                int m0 = wm + im * 16 + g;
                ah[im][0] = __float_as_uint(Ah[ks + t][m0]);
                ah[im][1] = __float_as_uint(Ah[ks + t][m0 + 8]);
                ah[im][2] = __float_as_uint(Ah[ks + t + 4][m0]);
                ah[im][3] = __float_as_uint(Ah[ks + t + 4][m0 + 8]);
                al[im][0] = __float_as_uint(Al[ks + t][m0]);
                al[im][1] = __float_as_uint(Al[ks + t][m0 + 8]);
                al[im][2] = __float_as_uint(Al[ks + t + 4][m0]);
                al[im][3] = __float_as_uint(Al[ks + t + 4][m0 + 8]);
            }
            #pragma unroll
            for (int jn = 0; jn < 8; jn++) {
                int n0 = wn + jn * 8 + g;
                unsigned bh0 = __float_as_uint(Bh[ks + t][n0]);
                unsigned bh1 = __float_as_uint(Bh[ks + t + 4][n0]);
                unsigned bl0 = __float_as_uint(Bl[ks + t][n0]);
                unsigned bl1 = __float_as_uint(Bl[ks + t + 4][n0]);
                #pragma unroll
                for (int im = 0; im < 2; im++) {
                    mma_tf32(c[im][jn], ah[im][0], ah[im][1], ah[im][2], ah[im][3], bl0, bl1);
                    mma_tf32(c[im][jn], al[im][0], al[im][1], al[im][2], al[im][3], bh0, bh1);
                    mma_tf32(c[im][jn], ah[im][0], ah[im][1], ah[im][2], ah[im][3], bh0, bh1);
                }
            }
        }
        if (have_next) {
            __syncthreads();
            #pragma unroll
            for (int i = 0; i < 2; i++) {
                float av[4] = {pa[i].x, pa[i].y, pa[i].z, pa[i].w};
                float bv[4] = {pb[i].x, pb[i].y, pb[i].z, pb[i].w};
                #pragma unroll
                for (int q = 0; q < 4; q++) {
                    unsigned h = f2tf32(av[q]);
                    Ah[akq[i] + q][amrow[i]] = __uint_as_float(h);
                    Al[akq[i] + q][amrow[i]] =
                        __uint_as_float(f2tf32(av[q] - __uint_as_float(h)));
                    unsigned hb = f2tf32(bv[q]);
                    Bh[bkr[i]][bnq[i] + q] = __uint_as_float(hb);
                    Bl[bkr[i]][bnq[i] + q] =
                        __uint_as_float(f2tf32(bv[q] - __uint_as_float(hb)));
                }
            }
            __syncthreads();
        }
    }

    #pragma unroll
    for (int im = 0; im < 2; im++) {
        #pragma unroll
        for (int half = 0; half < 2; half++) {
            int row = bm * 128 + wm + im * 16 + g + half * 8;
            float* Cp = C + (size_t)row * N + bn * 128 + wn;
            if (R) {
                const float* Rp = R + (size_t)row * N + bn * 128 + wn;
                #pragma unroll
                for (int jn = 0; jn < 8; jn++) {
                    Cp[jn * 8 + 2 * t]     = c[im][jn][half * 2 + 0] + Rp[jn * 8 + 2 * t];
                    Cp[jn * 8 + 2 * t + 1] = c[im][jn][half * 2 + 1] + Rp[jn * 8 + 2 * t + 1];
                }
            } else {
                #pragma unroll
                for (int jn = 0; jn < 8; jn++) {
                    Cp[jn * 8 + 2 * t]     = c[im][jn][half * 2 + 0];
                    Cp[jn * 8 + 2 * t + 1] = c[im][jn][half * 2 + 1];
                }
            }
        }
    }
}

// ------------------------- MoE grouped GEMM, TF32 tensor cores -------------------------
__global__ void __launch_bounds__(256, 2)
moe_mma_k(const float* __restrict__ X, const float* __restrict__ W,
          float* __restrict__ Cb, int K, int N, int gather) {
    const int e = blockIdx.z;
    const int cnt = g_cnt[e];
    const int bm = blockIdx.y;
    if (bm * 128 >= cnt) return;
    const int off = g_off[e];
    const int bn = blockIdx.x;
    const float* B = W + (size_t)e * K * N;
    float* C = Cb + (size_t)off * N;

    __shared__ float As[2][16][136];
    __shared__ float Bs[2][16][136];

    const int tid = threadIdx.x;
    const int warp = tid >> 5, lane = tid & 31;
    const int g = lane >> 2, t = lane & 3;
    const int wm = (warp & 3) * 32;
    const int wn = (warp >> 2) * 64;

    int amrow[2]; const float* aptr[2]; bool avalid[2];
    int akq[2];
    #pragma unroll
    for (int i = 0; i < 2; i++) {
        int task = tid + 256 * i;
        int mr = task >> 2;
        akq[i] = (task & 3) * 4;
        amrow[i] = mr;
        avalid[i] = (bm * 128 + mr) < cnt;
        int slot = off + bm * 128 + (avalid[i] ? mr : 0);
        int arow = gather ? g_perm[slot] : slot;
        aptr[i] = X + (size_t)arow * K + akq[i];
    }
    int bkr[2], bnq[2]; const float* bptr[2];
    #pragma unroll
    for (int i = 0; i < 2; i++) {
        int task = tid + 256 * i;
        bkr[i] = task >> 5;
        bnq[i] = (task & 31) * 4;
        bptr[i] = B + (size_t)bkr[i] * N + bn * 128 + bnq[i];
    }

    float c[2][8][4];
    #pragma unroll
    for (int im = 0; im < 2; im++)
        #pragma unroll
        for (int jn = 0; jn < 8; jn++)
            #pragma unroll
            for (int q = 0; q < 4; q++) c[im][jn][q] = 0.f;

    const int ntiles = K / 16;

    #pragma unroll
    for (int i = 0; i < 2; i++) {
        float4 av = avalid[i] ? *(const float4*)(aptr[i]) : make_float4(0, 0, 0, 0);
        As[0][akq[i] + 0][amrow[i]] = __uint_as_float(f2tf32(av.x));
        As[0][akq[i] + 1][amrow[i]] = __uint_as_float(f2tf32(av.y));
        As[0][akq[i] + 2][amrow[i]] = __uint_as_float(f2tf32(av.z));
        As[0][akq[i] + 3][amrow[i]] = __uint_as_float(f2tf32(av.w));
        float4 bv = *(const float4*)(bptr[i]);
        Bs[0][bkr[i]][bnq[i] + 0] = __uint_as_float(f2tf32(bv.x));
        Bs[0][bkr[i]][bnq[i] + 1] = __uint_as_float(f2tf32(bv.y));
        Bs[0][bkr[i]][bnq[i] + 2] = __uint_as_float(f2tf32(bv.z));
        Bs[0][bkr[i]][bnq[i] + 3] = __uint_as_float(f2tf32(bv.w));
    }
    __syncthreads();

    int cur = 0;
    for (int kt = 0; kt < ntiles; kt++) {
        float4 pa[2], pb[2];
        bool have_next = (kt + 1) < ntiles;
        if (have_next) {
            #pragma unroll
            for (int i = 0; i < 2; i++) {
                pa[i] = avalid[i] ? *(const float4*)(aptr[i] + (kt + 1) * 16)
                                  : make_float4(0, 0, 0, 0);
                pb[i] = *(const float4*)(bptr[i] + (size_t)(kt + 1) * 16 * N);
            }
        }
        #pragma unroll
        for (int ks = 0; ks < 16; ks += 8) {
            unsigned a0[2], a1[2], a2[2], a3[2];
            #pragma unroll
            for (int im = 0; im < 2; im++) {
                a0[im] = __float_as_uint(As[cur][ks + t][wm + im * 16 + g]);
                a1[im] = __float_as_uint(As[cur][ks + t][wm + im * 16 + 8 + g]);
                a2[im] = __float_as_uint(As[cur][ks + t + 4][wm + im * 16 + g]);
                a3[im] = __float_as_uint(As[cur][ks + t + 4][wm + im * 16 + 8 + g]);
            }
            #pragma unroll
            for (int jn = 0; jn < 8; jn++) {
                unsigned b0 = __float_as_uint(Bs[cur][ks + t][wn + jn * 8 + g]);
                unsigned b1 = __float_as_uint(Bs[cur][ks + t + 4][wn + jn * 8 + g]);
                #pragma unroll
                for (int im = 0; im < 2; im++)
                    mma_tf32(c[im][jn], a0[im], a1[im], a2[im], a3[im], b0, b1);
            }
        }
        if (have_next) {
            int nxt = cur ^ 1;
            #pragma unroll
            for (int i = 0; i < 2; i++) {
                As[nxt][akq[i] + 0][amrow[i]] = __uint_as_float(f2tf32(pa[i].x));
                As[nxt][akq[i] + 1][amrow[i]] = __uint_as_float(f2tf32(pa[i].y));
                As[nxt][akq[i] + 2][amrow[i]] = __uint_as_float(f2tf32(pa[i].z));
                As[nxt][akq[i] + 3][amrow[i]] = __uint_as_float(f2tf32(pa[i].w));
                Bs[nxt][bkr[i]][bnq[i] + 0] = __uint_as_float(f2tf32(pb[i].x));
                Bs[nxt][bkr[i]][bnq[i] + 1] = __uint_as_float(f2tf32(pb[i].y));
                Bs[nxt][bkr[i]][bnq[i] + 2] = __uint_as_float(f2tf32(pb[i].z));
                Bs[nxt][bkr[i]][bnq[i] + 3] = __uint_as_float(f2tf32(pb[i].w));
            }
            __syncthreads();
            cur = nxt;
        }
    }

    #pragma unroll
    for (int im = 0; im < 2; im++) {
        #pragma unroll
        for (int half = 0; half < 2; half++) {
            int rowl = bm * 128 + wm + im * 16 + g + half * 8;
            if (rowl < cnt) {
                float* Cp = C + (size_t)rowl * N + bn * 128 + wn;
                #pragma unroll
                for (int jn = 0; jn < 8; jn++) {
                    Cp[jn * 8 + 2 * t]     = c[im][jn][half * 2 + 0];
                    Cp[jn * 8 + 2 * t + 1] = c[im][jn][half * 2 + 1];
                }
            }
        }
    }
}

// ------------------------- RoPE -------------------------
__global__ void rope_tab_k() {
    int idx = blockIdx.x * blockDim.x + threadIdx.x;
    if (idx >= SEQ * 32) return;
    int s = idx >> 5, i = idx & 31;
    double invd = pow(10000.0, -(double)(2 * i) / 64.0);
    float f = (float)s * (float)invd;     // matches reference fp32 outer product
    g_cs[2 * idx]     = (float)cos((double)f);
    g_cs[2 * idx + 1] = (float)sin((double)f);
}

__global__ void rope_k(float* __restrict__ qkv) {
    int idx = blockIdx.x * blockDim.x + threadIdx.x;
    if (idx >= TOK * NHEAD * 32) return;
    int i = idx & 31;
    int h = (idx >> 5) & 15;
    int row = idx >> 9;
    int s = row & (SEQ - 1);
    float2 cs = *(const float2*)&g_cs[2 * (s * 32 + i)];
    float c = cs.x, sn = cs.y;
    float* qp = qkv + (size_t)row * TDIM + h * 64 + 2 * i;
    float xe = qp[0], xo = qp[1];
    qp[0] = xe * c - xo * sn;
    qp[1] = xe * sn + xo * c;
    float* kp = qp + DIM;
    xe = kp[0]; xo = kp[1];
    kp[0] = xe * c - xo * sn;
    kp[1] = xe * sn + xo * c;
}

// ------------------------- flash attention (64x64 tiles, hd=64) -------------------------
__global__ void attn_k(const float* __restrict__ qkv, float* __restrict__ out) {
    extern __shared__ float sm[];
    float* Qs = sm;                 // 64 x 65
    float* Ks = sm + 64 * 65;
    float* Vs = sm + 2 * 64 * 65;
    float* Ps = sm + 3 * 64 * 65;
    int mt = blockIdx.x;
    int b = blockIdx.y >> 4, h = blockIdx.y & 15;
    int tid = threadIdx.x;
    int ty = tid >> 4, tx = tid & 15;
    const size_t rowbase = (size_t)(b * SEQ) * TDIM;

    for (int i = tid; i < 64 * 64; i += 256) {
        int r = i >> 6, c = i & 63;
        Qs[r * 65 + c] = qkv[rowbase + (size_t)(mt * 64 + r) * TDIM + h * 64 + c];
    }
    float m_i[4], l_i[4], o[4][4];
    #pragma unroll
    for (int i = 0; i < 4; i++) {
        m_i[i] = -INFINITY; l_i[i] = 0.f;
        #pragma unroll
        for (int j = 0; j < 4; j++) o[i][j] = 0.f;
    }

    for (int nt = 0; nt <= mt; nt++) {
        __syncthreads();
        for (int i = tid; i < 64 * 64; i += 256) {
            int r = i >> 6, c = i & 63;
            size_t base = rowbase + (size_t)(nt * 64 + r) * TDIM + h * 64 + c;
            Ks[r * 65 + c] = qkv[base + DIM];
            Vs[r * 65 + c] = qkv[base + 2 * DIM];
        }
        __syncthreads();

        float s4[4][4];
        #pragma unroll
        for (int i = 0; i < 4; i++)
            #pragma unroll
            for (int j = 0; j < 4; j++) s4[i][j] = 0.f;
        #pragma unroll 8
        for (int d = 0; d < 64; d++) {
            float a[4], k4[4];
            #pragma unroll
            for (int i = 0; i < 4; i++) a[i] = Qs[(ty * 4 + i) * 65 + d];
            #pragma unroll
            for (int j = 0; j < 4; j++) k4[j] = Ks[(tx * 4 + j) * 65 + d];
            #pragma unroll
            for (int i = 0; i < 4; i++)
                #pragma unroll
                for (int j = 0; j < 4; j++)
                    s4[i][j] = fmaf(a[i], k4[j], s4[i][j]);
        }
        const float scale = 0.125f;
        #pragma unroll
        for (int i = 0; i < 4; i++) {
            #pragma unroll
            for (int j = 0; j < 4; j++) {
                float v = s4[i][j] * scale;
                if (nt == mt && (tx * 4 + j) > (ty * 4 + i)) v = -INFINITY;
                s4[i][j] = v;
            }
            float mx = fmaxf(fmaxf(s4[i][0], s4[i][1]), fmaxf(s4[i][2], s4[i][3]));
            #pragma unroll
            for (int o2 = 8; o2; o2 >>= 1) mx = fmaxf(mx, __shfl_xor_sync(0xffffffffu, mx, o2, 16));
            float mn = fmaxf(m_i[i], mx);
            float alpha = expf(m_i[i] - mn);
            float rsum = 0.f;
            #pragma unroll
            for (int j = 0; j < 4; j++) {
                float p = expf(s4[i][j] - mn);
                Ps[(ty * 4 + i) * 65 + tx * 4 + j] = p;
                rsum += p;
            }
            #pragma unroll
            for (int o2 = 8; o2; o2 >>= 1) rsum += __shfl_xor_sync(0xffffffffu, rsum, o2, 16);
            l_i[i] = l_i[i] * alpha + rsum;
            m_i[i] = mn;
            #pragma unroll
            for (int j = 0; j < 4; j++) o[i][j] *= alpha;
        }
        __syncthreads();
        #pragma unroll 8
        for (int n = 0; n < 64; n++) {
            float p4[4], v4[4];
            #pragma unroll
            for (int i = 0; i < 4; i++) p4[i] = Ps[(ty * 4 + i) * 65 + n];
            #pragma unroll
            for (int j = 0; j < 4; j++) v4[j] = Vs[n * 65 + tx * 4 + j];
            #pragma unroll
            for (int i = 0; i < 4; i++)
                #pragma unroll
                for (int j = 0; j < 4; j++)
                    o[i][j] = fmaf(p4[i], v4[j], o[i][j]);
        }
    }
    #pragma unroll
    for (int i = 0; i < 4; i++) {
        float inv = 1.f / l_i[i];
        #pragma unroll
        for (int j = 0; j < 4; j++)
            out[(size_t)(b * SEQ + mt * 64 + ty * 4 + i) * DIM + h * 64 + tx * 4 + j] = o[i][j] * inv;
    }
}

// ------------------------- MoE gate / routing -------------------------
__global__ void zero_k() {
    int t = threadIdx.x;
    if (t < NEXP) { g_cnt[t] = 0; g_fill[t] = 0; g_dist[t] = 0.f; }
}

__global__ void gate_k(const float* __restrict__ xn2, const float* __restrict__ gw) {
    int t = blockIdx.x;
    int wid = threadIdx.x >> 5, lane = threadIdx.x & 31;
    const float* xr = xn2 + (size_t)t * DIM;
    float acc = 0.f;
    for (int k = lane; k < DIM; k += 32) {
        float a = __bfloat162float(__float2bfloat16(xr[k]));
        float w = __bfloat162float(__float2bfloat16(gw[(size_t)k * NEXP + wid]));
        acc = fmaf(a, w, acc);
    }
    #pragma unroll
    for (int o = 16; o; o >>= 1) acc += __shfl_xor_sync(0xffffffffu, acc, o);
    __shared__ float lg[NEXP];
    if (lane == 0) lg[wid] = __bfloat162float(__float2bfloat16(acc));  // bf16 result like jax
    __syncthreads();
    if (threadIdx.x == 0) {
        float mx = lg[0];
        for (int e = 1; e < NEXP; e++) mx = fmaxf(mx, lg[e]);
        float p[NEXP], sum = 0.f;
        for (int e = 0; e < NEXP; e++) { p[e] = expf(lg[e] - mx); sum += p[e]; }
        float inv = 1.f / sum;
        for (int e = 0; e < NEXP; e++) atomicAdd(&g_dist[e], p[e] * inv);
        int i0 = 0;
        for (int e = 1; e < NEXP; e++) if (lg[e] > lg[i0]) i0 = e;
        int i1 = -1;
        for (int e = 0; e < NEXP; e++) {
            if (e == i0) continue;
            if (i1 < 0 || lg[e] > lg[i1]) i1 = e;
        }
        float eb = expf(lg[i1] - lg[i0]);
        float w0 = 1.f / (1.f + eb);
        g_cw[2 * t] = w0;
        g_cw[2 * t + 1] = eb * w0;
        g_topk[2 * t] = i0;
        g_topk[2 * t + 1] = i1;
        atomicAdd(&g_cnt[i0], 1);
        atomicAdd(&g_cnt[i1], 1);
    }
}

__global__ void offsets_k() {
    if (threadIdx.x == 0) {
        int a = 0;
        for (int e = 0; e < NEXP; e++) { g_off[e] = a; a += g_cnt[e]; }
    }
}

__global__ void fill_k() {
    int t = blockIdx.x * blockDim.x + threadIdx.x;
    if (t >= TOK) return;
    for (int k2 = 0; k2 < 2; k2++) {
        int e = g_topk[2 * t + k2];
        int pos = g_off[e] + atomicAdd(&g_fill[e], 1);
        g_perm[pos] = t;
        g_slot[2 * t + k2] = pos;
    }
}

__global__ void silu_k() {
    int i = blockIdx.x * blockDim.x + threadIdx.x;
    if (i >= SLOTS * HID) return;
    float g = g_gbuf[i], u = g_ubuf[i];
    g_gbuf[i] = g / (1.f + expf(-g)) * u;
}

__global__ void epi_k(float* __restrict__ out) {
    int i = blockIdx.x * blockDim.x + threadIdx.x;
    if (i >= TOK * DIM) return;
    int t = i >> 10, d = i & 1023;
    float r = g_x1[i];
    r += g_cw[2 * t] * g_dbuf[(size_t)g_slot[2 * t] * DIM + d];
    r += g_cw[2 * t + 1] * g_dbuf[(size_t)g_slot[2 * t + 1] * DIM + d];
    out[i] = r;
}

__global__ void fin_k(float* __restrict__ out) {
    if (threadIdx.x == 0 && blockIdx.x == 0) {
        float s = 0.f;
        for (int e = 0; e < NEXP; e++) {
            float d = g_dist[e] * (1.f / 2048.f);
            out[TOK * DIM + 1 + e] = d;
            s += d * d;
        }
        out[TOK * DIM] = 8.f * s;
    }
}

// ------------------------- launch -------------------------
extern "C" void kernel_launch(void* const* d_in, const int* in_sizes, int n_in,
                              void* d_out, int out_size) {
    const float* x    = (const float*)d_in[0];
    const float* ln1g = (const float*)d_in[1];
    const float* ln1b = (const float*)d_in[2];
    const float* ln2g = (const float*)d_in[3];
    const float* ln2b = (const float*)d_in[4];
    const float* wqkv = (const float*)d_in[5];
    const float* wo   = (const float*)d_in[6];
    const float* gw   = (const float*)d_in[7];
    const float* wg   = (const float*)d_in[8];
    const float* wu   = (const float*)d_in[9];
    const float* wd   = (const float*)d_in[10];
    float* out = (float*)d_out;

    float *pxn1, *pqkv, *pattn, *px1, *pxn2, *pg, *pu, *pd;
    cudaGetSymbolAddress((void**)&pxn1, g_xn1);
    cudaGetSymbolAddress((void**)&pqkv, g_qkv);
    cudaGetSymbolAddress((void**)&pattn, g_attn);
    cudaGetSymbolAddress((void**)&px1, g_x1);
    cudaGetSymbolAddress((void**)&pxn2, g_xn2);
    cudaGetSymbolAddress((void**)&pg, g_gbuf);
    cudaGetSymbolAddress((void**)&pu, g_ubuf);
    cudaGetSymbolAddress((void**)&pd, g_dbuf);

    cudaFuncSetAttribute(attn_k, cudaFuncAttributeMaxDynamicSharedMemorySize, 4 * 64 * 65 * 4);

    zero_k<<<1, 32>>>();
    rope_tab_k<<<(SEQ * 32 + 255) / 256, 256>>>();
    ln_k<<<TOK, 256>>>(x, ln1g, ln1b, pxn1);
    gemm3x_k<<<dim3(TDIM / 128, TOK / 128), 256>>>(pxn1, wqkv, pqkv, nullptr, TDIM, DIM);
    rope_k<<<(TOK * NHEAD * 32 + 255) / 256, 256>>>(pqkv);
    attn_k<<<dim3(SEQ / 64, 4 * NHEAD), 256, 4 * 64 * 65 * 4>>>(pqkv, pattn);
    gemm3x_k<<<dim3(DIM / 128, TOK / 128), 256>>>(pattn, wo, px1, x, DIM, DIM);
    ln_k<<<TOK, 256>>>(px1, ln2g, ln2b, pxn2);
    gate_k<<<TOK, 256>>>(pxn2, gw);
    offsets_k<<<1, 1>>>();
    fill_k<<<(TOK + 255) / 256, 256>>>();
    moe_mma_k<<<dim3(HID / 128, 32, NEXP), 256>>>(pxn2, wg, pg, DIM, HID, 1);
    moe_mma_k<<<dim3(HID / 128, 32, NEXP), 256>>>(pxn2, wu, pu, DIM, HID, 1);
    silu_k<<<(SLOTS * HID + 255) / 256, 256>>>();
    moe_mma_k<<<dim3(DIM / 128, 32, NEXP), 256>>>(pg, wd, pd, HID, DIM, 0);
    epi_k<<<(TOK * DIM + 255) / 256, 256>>>(out);
    fin_k<<<1, 1>>>(out);
}